// round 1
// baseline (speedup 1.0000x reference)
#include <cuda_runtime.h>
#include <cuda_bf16.h>
#include <mma.h>

using namespace nvcuda;

#define B_SZ 16
#define N_SZ 2048
#define HID  128

// fp32 scratch (no allocation allowed -> __device__ globals)
__device__ float g_p[B_SZ * N_SZ * HID];   // 16 MB: projected features h @ W
__device__ float g_h[B_SZ * N_SZ * HID];   // 16 MB: layer output

// shared-memory strides (in floats)
#define SA_LD 36     // agg A tile: 128 x 32, pad to 36 (mult of 4 for wmma ldm)
#define SB_LD 132    // B/C tiles: 128-wide, pad to 132
#define SC_LD 132

#define PW_SMEM  (2 * 128 * 132 * 4)                       // 135168 B
#define AGG_SMEM ((128 * 132 + 256) * 4)                   //  68608 B

// ---------------------------------------------------------------------------
// pw_kernel: out[r, :] = src[r, :] @ W   (rows flattened over B*N, K=N=128)
// tf32 wmma, one CTA = 128 rows, 8 warps in 4x2 layout, each warp 32x64.
// ---------------------------------------------------------------------------
__global__ __launch_bounds__(256) void pw_kernel(const float* __restrict__ src,
                                                 const float* __restrict__ W,
                                                 float* __restrict__ out)
{
    extern __shared__ float sm[];
    float* sA = sm;                    // 128 x 132
    float* sB = sm + 128 * 132;        // 128 x 132
    float* sC = sm;                    // overlays sA after compute

    const int tid  = threadIdx.x;
    const int warp = tid >> 5;
    const int wr   = warp >> 1;        // 0..3 (row group of 32)
    const int wc   = warp & 1;         // 0..1 (col group of 64)
    const size_t row0 = (size_t)blockIdx.x * 128;

    // load A (src rows) and B (W) into padded smem, fp32
    #pragma unroll
    for (int i = tid; i < 128 * 32; i += 256) {
        int r = i >> 5, c4 = i & 31;
        float4 v = *(const float4*)(src + (row0 + r) * HID + c4 * 4);
        *(float4*)(sA + r * SB_LD + c4 * 4) = v;
    }
    #pragma unroll
    for (int i = tid; i < 128 * 32; i += 256) {
        int r = i >> 5, c4 = i & 31;
        float4 v = *(const float4*)(W + r * HID + c4 * 4);
        *(float4*)(sB + r * SB_LD + c4 * 4) = v;
    }
    __syncthreads();

    wmma::fragment<wmma::accumulator, 16, 16, 8, float> acc[2][4];
    #pragma unroll
    for (int i = 0; i < 2; i++)
        #pragma unroll
        for (int j = 0; j < 4; j++) wmma::fill_fragment(acc[i][j], 0.f);

    #pragma unroll
    for (int ks = 0; ks < 16; ++ks) {   // K=128, k-step 8
        wmma::fragment<wmma::matrix_a, 16, 16, 8, wmma::precision::tf32, wmma::row_major> fa[2];
        wmma::fragment<wmma::matrix_b, 16, 16, 8, wmma::precision::tf32, wmma::row_major> fb[4];
        #pragma unroll
        for (int i = 0; i < 2; i++) {
            wmma::load_matrix_sync(fa[i], sA + (wr * 32 + i * 16) * SB_LD + ks * 8, SB_LD);
            #pragma unroll
            for (int t = 0; t < fa[i].num_elements; t++)
                fa[i].x[t] = wmma::__float_to_tf32(fa[i].x[t]);
        }
        #pragma unroll
        for (int j = 0; j < 4; j++) {
            wmma::load_matrix_sync(fb[j], sB + (ks * 8) * SB_LD + wc * 64 + j * 16, SB_LD);
            #pragma unroll
            for (int t = 0; t < fb[j].num_elements; t++)
                fb[j].x[t] = wmma::__float_to_tf32(fb[j].x[t]);
        }
        #pragma unroll
        for (int i = 0; i < 2; i++)
            #pragma unroll
            for (int j = 0; j < 4; j++)
                wmma::mma_sync(acc[i][j], fa[i], fb[j], acc[i][j]);
    }
    __syncthreads();   // all smem reads done before overlaying with C

    #pragma unroll
    for (int i = 0; i < 2; i++)
        #pragma unroll
        for (int j = 0; j < 4; j++)
            wmma::store_matrix_sync(sC + (wr * 32 + i * 16) * SC_LD + wc * 64 + j * 16,
                                    acc[i][j], SC_LD, wmma::mem_row_major);
    __syncthreads();

    #pragma unroll
    for (int i = tid; i < 128 * 32; i += 256) {
        int r = i >> 5, c4 = i & 31;
        float4 v = *(const float4*)(sC + r * SC_LD + c4 * 4);
        *(float4*)(out + (row0 + r) * HID + c4 * 4) = v;
    }
}

// ---------------------------------------------------------------------------
// agg_kernel: C[128x128] = adj[b, n0:n0+128, :] @ p[b, :, :], then
// epilogue: +bias, LayerNorm over 128 cols, *gamma+beta, ReLU -> out fp32.
// ---------------------------------------------------------------------------
__global__ __launch_bounds__(256, 2) void agg_kernel(const float* __restrict__ adj,
                                                     const float* __restrict__ p,
                                                     const float* __restrict__ bias,
                                                     const float* __restrict__ gamma,
                                                     const float* __restrict__ beta,
                                                     float* __restrict__ out)
{
    extern __shared__ float sm[];
    float* sA  = sm;                       // 128 x 36
    float* sB  = sm + 128 * SA_LD;         // 32 x 132
    float* sC  = sm;                       // 128 x 132 (overlays A/B after loop)
    float* sMu = sm + 128 * SC_LD;         // 128
    float* sRs = sMu + 128;                // 128

    const int tid  = threadIdx.x;
    const int warp = tid >> 5;
    const int wr   = warp >> 1;
    const int wc   = warp & 1;
    const int b    = blockIdx.y;
    const int n0   = blockIdx.x * 128;

    const float* adjb = adj + (size_t)b * N_SZ * N_SZ;
    const float* pb   = p   + (size_t)b * N_SZ * HID;

    wmma::fragment<wmma::accumulator, 16, 16, 8, float> acc[2][4];
    #pragma unroll
    for (int i = 0; i < 2; i++)
        #pragma unroll
        for (int j = 0; j < 4; j++) wmma::fill_fragment(acc[i][j], 0.f);

    for (int k0 = 0; k0 < N_SZ; k0 += 32) {
        // A: 128 x 32 fp32 slab of adj
        #pragma unroll
        for (int it = 0; it < 4; ++it) {
            int i = tid + it * 256;
            int r = i >> 3, c4 = i & 7;
            float4 v = *(const float4*)(adjb + (size_t)(n0 + r) * N_SZ + k0 + c4 * 4);
            *(float4*)(sA + r * SA_LD + c4 * 4) = v;
        }
        // B: 32 x 128 fp32 slab of p
        #pragma unroll
        for (int it = 0; it < 4; ++it) {
            int i = tid + it * 256;
            int r = i >> 5, s = i & 31;
            float4 v = *(const float4*)(pb + (size_t)(k0 + r) * HID + s * 4);
            *(float4*)(sB + r * SB_LD + s * 4) = v;
        }
        __syncthreads();

        #pragma unroll
        for (int ks = 0; ks < 4; ++ks) {   // 32 / k-step 8
            wmma::fragment<wmma::matrix_a, 16, 16, 8, wmma::precision::tf32, wmma::row_major> fa[2];
            wmma::fragment<wmma::matrix_b, 16, 16, 8, wmma::precision::tf32, wmma::row_major> fb[4];
            #pragma unroll
            for (int i = 0; i < 2; i++) {
                wmma::load_matrix_sync(fa[i], sA + (wr * 32 + i * 16) * SA_LD + ks * 8, SA_LD);
                #pragma unroll
                for (int t = 0; t < fa[i].num_elements; t++)
                    fa[i].x[t] = wmma::__float_to_tf32(fa[i].x[t]);
            }
            #pragma unroll
            for (int j = 0; j < 4; j++) {
                wmma::load_matrix_sync(fb[j], sB + (ks * 8) * SB_LD + wc * 64 + j * 16, SB_LD);
                #pragma unroll
                for (int t = 0; t < fb[j].num_elements; t++)
                    fb[j].x[t] = wmma::__float_to_tf32(fb[j].x[t]);
            }
            #pragma unroll
            for (int i = 0; i < 2; i++)
                #pragma unroll
                for (int j = 0; j < 4; j++)
                    wmma::mma_sync(acc[i][j], fa[i], fb[j], acc[i][j]);
        }
        __syncthreads();
    }

    // dump accumulators to smem for the row-wise epilogue
    #pragma unroll
    for (int i = 0; i < 2; i++)
        #pragma unroll
        for (int j = 0; j < 4; j++)
            wmma::store_matrix_sync(sC + (wr * 32 + i * 16) * SC_LD + wc * 64 + j * 16,
                                    acc[i][j], SC_LD, wmma::mem_row_major);
    __syncthreads();

    // per-row LayerNorm stats (one thread per row)
    if (tid < 128) {
        const float* r = sC + tid * SC_LD;
        float s = 0.f, s2 = 0.f;
        #pragma unroll 8
        for (int c = 0; c < 128; c++) {
            float v = r[c] + __ldg(&bias[c]);
            s  += v;
            s2 += v * v;
        }
        float mu  = s * (1.f / 128.f);
        float var = s2 * (1.f / 128.f) - mu * mu;
        sMu[tid] = mu;
        sRs[tid] = rsqrtf(var + 1e-5f);
    }
    __syncthreads();

    // coalesced normalize + relu + write
    float* ob = out + ((size_t)b * N_SZ + n0) * HID;
    #pragma unroll
    for (int i = tid; i < 128 * 128; i += 256) {
        int r = i >> 7, c = i & 127;
        float v = sC[r * SC_LD + c] + __ldg(&bias[c]);
        v = (v - sMu[r]) * sRs[r] * __ldg(&gamma[c]) + __ldg(&beta[c]);
        ob[(size_t)r * HID + c] = fmaxf(v, 0.f);
    }
}

// ---------------------------------------------------------------------------
extern "C" void kernel_launch(void* const* d_in, const int* in_sizes, int n_in,
                              void* d_out, int out_size)
{
    const float* x   = (const float*)d_in[0];
    const float* adj = (const float*)d_in[1];
    const float* W[3]  = {(const float*)d_in[2],  (const float*)d_in[6],  (const float*)d_in[10]};
    const float* bb[3] = {(const float*)d_in[3],  (const float*)d_in[7],  (const float*)d_in[11]};
    const float* gg[3] = {(const float*)d_in[4],  (const float*)d_in[8],  (const float*)d_in[12]};
    const float* be[3] = {(const float*)d_in[5],  (const float*)d_in[9],  (const float*)d_in[13]};
    float* out = (float*)d_out;

    cudaFuncSetAttribute(pw_kernel,  cudaFuncAttributeMaxDynamicSharedMemorySize, PW_SMEM);
    cudaFuncSetAttribute(agg_kernel, cudaFuncAttributeMaxDynamicSharedMemorySize, AGG_SMEM);

    float *pp, *ph;
    cudaGetSymbolAddress((void**)&pp, g_p);
    cudaGetSymbolAddress((void**)&ph, g_h);

    dim3 aggGrid(N_SZ / 128, B_SZ);   // (16, 16)
    const float* h = x;
    for (int l = 0; l < 3; ++l) {
        // p = h @ W   (the dense layer, hoisted before the aggregation GEMM)
        pw_kernel<<<(B_SZ * N_SZ) / 128, 256, PW_SMEM>>>(h, W[l], pp);
        // h_next = relu(LN(adj @ p + b))
        float* dst = (l == 2) ? out : ph;
        agg_kernel<<<aggGrid, 256, AGG_SMEM>>>(adj, pp, bb[l], gg[l], be[l], dst);
        h = ph;
    }
}

// round 3
// speedup vs baseline: 1.0223x; 1.0223x over previous
#include <cuda_runtime.h>
#include <cuda_bf16.h>
#include <mma.h>
#include <cstdint>

using namespace nvcuda;

#define B_SZ 16
#define N_SZ 2048
#define HID  128

// fp32 scratch (no allocation allowed -> __device__ globals)
__device__ float g_p[B_SZ * N_SZ * HID];   // 16 MB: projected features h @ W
__device__ float g_h[B_SZ * N_SZ * HID];   // 16 MB: layer output

// shared-memory strides (in floats)
#define SA_LD 36     // agg A tile: 128 x 32, pad to 36 (144B rows, 16B aligned)
#define SB_LD 132    // B/C tiles: 128-wide, pad to 132 (528B rows, 16B aligned)
#define SC_LD 132

#define STAGES 3
#define KC     32
#define A_STG  (128 * SA_LD)           // floats per A stage  (4608)
#define B_STG  (KC * SB_LD)            // floats per B stage  (4224)
#define B_BASE (STAGES * A_STG)        // 13824
#define STAT_BASE (B_BASE + STAGES * B_STG)   // 26496
#define AGG_SMEM ((STAT_BASE + 256) * 4)      // 107008 B
#define PW_SMEM  (2 * 128 * 132 * 4)          // 135168 B

// ---------------------------------------------------------------------------
__device__ __forceinline__ void cp_async16(float* smem, const float* gmem) {
    unsigned s = (unsigned)__cvta_generic_to_shared(smem);
    asm volatile("cp.async.cg.shared.global [%0], [%1], 16;\n" :: "r"(s), "l"(gmem));
}
__device__ __forceinline__ void cp_commit() {
    asm volatile("cp.async.commit_group;\n");
}
template<int N> __device__ __forceinline__ void cp_wait() {
    asm volatile("cp.async.wait_group %0;\n" :: "n"(N));
}

// ---------------------------------------------------------------------------
// pw_kernel: out[r, :] = src[r, :] @ W   (rows flattened over B*N, K=N=128)
// ---------------------------------------------------------------------------
__global__ __launch_bounds__(256) void pw_kernel(const float* __restrict__ src,
                                                 const float* __restrict__ W,
                                                 float* __restrict__ out)
{
    extern __shared__ float sm[];
    float* sA = sm;                    // 128 x 132
    float* sB = sm + 128 * 132;        // 128 x 132
    float* sC = sm;                    // overlays sA after compute

    const int tid  = threadIdx.x;
    const int warp = tid >> 5;
    const int wr   = warp >> 1;
    const int wc   = warp & 1;
    const size_t row0 = (size_t)blockIdx.x * 128;

    #pragma unroll
    for (int i = tid; i < 128 * 32; i += 256) {
        int r = i >> 5, c4 = i & 31;
        cp_async16(sA + r * SB_LD + c4 * 4, src + (row0 + r) * HID + c4 * 4);
    }
    #pragma unroll
    for (int i = tid; i < 128 * 32; i += 256) {
        int r = i >> 5, c4 = i & 31;
        cp_async16(sB + r * SB_LD + c4 * 4, W + r * HID + c4 * 4);
    }
    cp_commit();
    cp_wait<0>();
    __syncthreads();

    wmma::fragment<wmma::accumulator, 16, 16, 8, float> acc[2][4];
    #pragma unroll
    for (int i = 0; i < 2; i++)
        #pragma unroll
        for (int j = 0; j < 4; j++) wmma::fill_fragment(acc[i][j], 0.f);

    #pragma unroll
    for (int ks = 0; ks < 16; ++ks) {
        wmma::fragment<wmma::matrix_a, 16, 16, 8, wmma::precision::tf32, wmma::row_major> fa[2];
        wmma::fragment<wmma::matrix_b, 16, 16, 8, wmma::precision::tf32, wmma::row_major> fb[4];
        #pragma unroll
        for (int i = 0; i < 2; i++) {
            wmma::load_matrix_sync(fa[i], sA + (wr * 32 + i * 16) * SB_LD + ks * 8, SB_LD);
            #pragma unroll
            for (int t = 0; t < fa[i].num_elements; t++)
                fa[i].x[t] = wmma::__float_to_tf32(fa[i].x[t]);
        }
        #pragma unroll
        for (int j = 0; j < 4; j++) {
            wmma::load_matrix_sync(fb[j], sB + (ks * 8) * SB_LD + wc * 64 + j * 16, SB_LD);
            #pragma unroll
            for (int t = 0; t < fb[j].num_elements; t++)
                fb[j].x[t] = wmma::__float_to_tf32(fb[j].x[t]);
        }
        #pragma unroll
        for (int i = 0; i < 2; i++)
            #pragma unroll
            for (int j = 0; j < 4; j++)
                wmma::mma_sync(acc[i][j], fa[i], fb[j], acc[i][j]);
    }
    __syncthreads();

    #pragma unroll
    for (int i = 0; i < 2; i++)
        #pragma unroll
        for (int j = 0; j < 4; j++)
            wmma::store_matrix_sync(sC + (wr * 32 + i * 16) * SC_LD + wc * 64 + j * 16,
                                    acc[i][j], SC_LD, wmma::mem_row_major);
    __syncthreads();

    #pragma unroll
    for (int i = tid; i < 128 * 32; i += 256) {
        int r = i >> 5, c4 = i & 31;
        float4 v = *(const float4*)(sC + r * SC_LD + c4 * 4);
        *(float4*)(out + (row0 + r) * HID + c4 * 4) = v;
    }
}

// ---------------------------------------------------------------------------
// agg_kernel: C[128x128] = adj[b, n0:n0+128, :] @ p[b, :, :]; fused epilogue
// (+bias, LayerNorm over 128 cols, *gamma+beta, ReLU).
// 3-stage cp.async pipeline, KC=32.
// ---------------------------------------------------------------------------
__device__ __forceinline__ void agg_load_stage(float* sm, int stg,
                                               const float* __restrict__ adjb,
                                               const float* __restrict__ pb,
                                               int n0, int k0, int tid)
{
    float* sA = sm + stg * A_STG;
    float* sB = sm + B_BASE + stg * B_STG;
    #pragma unroll
    for (int it = 0; it < 4; ++it) {
        int i = tid + it * 256;
        int r = i >> 3, c4 = i & 7;
        cp_async16(sA + r * SA_LD + c4 * 4,
                   adjb + (size_t)(n0 + r) * N_SZ + k0 + c4 * 4);
    }
    #pragma unroll
    for (int it = 0; it < 4; ++it) {
        int i = tid + it * 256;
        int r = i >> 5, s = i & 31;
        cp_async16(sB + r * SB_LD + s * 4,
                   pb + (size_t)(k0 + r) * HID + s * 4);
    }
    cp_commit();
}

__global__ __launch_bounds__(256, 2) void agg_kernel(const float* __restrict__ adj,
                                                     const float* __restrict__ p,
                                                     const float* __restrict__ bias,
                                                     const float* __restrict__ gamma,
                                                     const float* __restrict__ beta,
                                                     float* __restrict__ out)
{
    extern __shared__ float sm[];
    float* sC  = sm;                   // 128 x 132 (overlays stage buffers at end)
    float* sMu = sm + STAT_BASE;       // 128
    float* sRs = sMu + 128;            // 128

    const int tid  = threadIdx.x;
    const int warp = tid >> 5;
    const int wr   = warp >> 1;
    const int wc   = warp & 1;
    const int b    = blockIdx.y;
    const int n0   = blockIdx.x * 128;

    const float* adjb = adj + (size_t)b * N_SZ * N_SZ;
    const float* pb   = p   + (size_t)b * N_SZ * HID;

    wmma::fragment<wmma::accumulator, 16, 16, 8, float> acc[2][4];
    #pragma unroll
    for (int i = 0; i < 2; i++)
        #pragma unroll
        for (int j = 0; j < 4; j++) wmma::fill_fragment(acc[i][j], 0.f);

    // prologue: preload STAGES-1 stages
    agg_load_stage(sm, 0, adjb, pb, n0, 0, tid);
    agg_load_stage(sm, 1, adjb, pb, n0, KC, tid);

    const int NT = N_SZ / KC;   // 64
    for (int kt = 0; kt < NT; ++kt) {
        cp_wait<STAGES - 2>();
        __syncthreads();   // stage kt data visible

        int nk = kt + STAGES - 1;
        if (nk < NT)
            agg_load_stage(sm, nk % STAGES, adjb, pb, n0, nk * KC, tid);

        const int stg = kt % STAGES;
        float* sA = sm + stg * A_STG;
        float* sB = sm + B_BASE + stg * B_STG;

        #pragma unroll
        for (int ks = 0; ks < KC / 8; ++ks) {
            wmma::fragment<wmma::matrix_a, 16, 16, 8, wmma::precision::tf32, wmma::row_major> fa[2];
            wmma::fragment<wmma::matrix_b, 16, 16, 8, wmma::precision::tf32, wmma::row_major> fb[4];
            #pragma unroll
            for (int i = 0; i < 2; i++) {
                wmma::load_matrix_sync(fa[i], sA + (wr * 32 + i * 16) * SA_LD + ks * 8, SA_LD);
                #pragma unroll
                for (int t = 0; t < fa[i].num_elements; t++)
                    fa[i].x[t] = wmma::__float_to_tf32(fa[i].x[t]);
            }
            #pragma unroll
            for (int j = 0; j < 4; j++) {
                wmma::load_matrix_sync(fb[j], sB + (ks * 8) * SB_LD + wc * 64 + j * 16, SB_LD);
                #pragma unroll
                for (int t = 0; t < fb[j].num_elements; t++)
                    fb[j].x[t] = wmma::__float_to_tf32(fb[j].x[t]);
            }
            #pragma unroll
            for (int i = 0; i < 2; i++)
                #pragma unroll
                for (int j = 0; j < 4; j++)
                    wmma::mma_sync(acc[i][j], fa[i], fb[j], acc[i][j]);
        }
    }
    __syncthreads();   // all compute done before overlaying stage smem with C

    #pragma unroll
    for (int i = 0; i < 2; i++)
        #pragma unroll
        for (int j = 0; j < 4; j++)
            wmma::store_matrix_sync(sC + (wr * 32 + i * 16) * SC_LD + wc * 64 + j * 16,
                                    acc[i][j], SC_LD, wmma::mem_row_major);
    __syncthreads();

    // per-row LayerNorm stats: 2 threads per row (64 cols each), shfl combine
    {
        int r = tid >> 1, half = tid & 1;
        const float* rp = sC + r * SC_LD + half * 64;
        const float* bp = bias + half * 64;
        float s = 0.f, s2 = 0.f;
        #pragma unroll 8
        for (int c = 0; c < 64; c++) {
            float v = rp[c] + __ldg(&bp[c]);
            s  += v;
            s2 += v * v;
        }
        s  += __shfl_xor_sync(0xFFFFFFFF, s, 1);
        s2 += __shfl_xor_sync(0xFFFFFFFF, s2, 1);
        if (half == 0) {
            float mu  = s * (1.f / 128.f);
            float var = s2 * (1.f / 128.f) - mu * mu;
            sMu[r] = mu;
            sRs[r] = rsqrtf(var + 1e-5f);
        }
    }
    __syncthreads();

    float* ob = out + ((size_t)b * N_SZ + n0) * HID;
    #pragma unroll
    for (int i = tid; i < 128 * 128; i += 256) {
        int r = i >> 7, c = i & 127;
        float v = sC[r * SC_LD + c] + __ldg(&bias[c]);
        v = (v - sMu[r]) * sRs[r] * __ldg(&gamma[c]) + __ldg(&beta[c]);
        ob[(size_t)r * HID + c] = fmaxf(v, 0.f);
    }
}

// ---------------------------------------------------------------------------
extern "C" void kernel_launch(void* const* d_in, const int* in_sizes, int n_in,
                              void* d_out, int out_size)
{
    const float* x   = (const float*)d_in[0];
    const float* adj = (const float*)d_in[1];
    const float* W[3]  = {(const float*)d_in[2],  (const float*)d_in[6],  (const float*)d_in[10]};
    const float* bb[3] = {(const float*)d_in[3],  (const float*)d_in[7],  (const float*)d_in[11]};
    const float* gg[3] = {(const float*)d_in[4],  (const float*)d_in[8],  (const float*)d_in[12]};
    const float* be[3] = {(const float*)d_in[5],  (const float*)d_in[9],  (const float*)d_in[13]};
    float* out = (float*)d_out;

    cudaFuncSetAttribute(pw_kernel,  cudaFuncAttributeMaxDynamicSharedMemorySize, PW_SMEM);
    cudaFuncSetAttribute(agg_kernel, cudaFuncAttributeMaxDynamicSharedMemorySize, AGG_SMEM);

    float *pp, *ph;
    cudaGetSymbolAddress((void**)&pp, g_p);
    cudaGetSymbolAddress((void**)&ph, g_h);

    dim3 aggGrid(N_SZ / 128, B_SZ);   // (16, 16)
    const float* h = x;
    for (int l = 0; l < 3; ++l) {
        pw_kernel<<<(B_SZ * N_SZ) / 128, 256, PW_SMEM>>>(h, W[l], pp);
        float* dst = (l == 2) ? out : ph;
        agg_kernel<<<aggGrid, 256, AGG_SMEM>>>(adj, pp, bb[l], gg[l], be[l], dst);
        h = ph;
    }
}